// round 6
// baseline (speedup 1.0000x reference)
#include <cuda_runtime.h>

#define B_ 4
#define C_ 8
#define F_ 512
#define T_ 1000

#define SPEC_N 16384000ll   // B*C*F*T

// -------- device scratch (sanctioned alternative to cudaMalloc) --------
__device__ float d_psd[2][B_][F_][C_][C_][2];   // [S/N][b][f][r][e][re,im]
__device__ float d_minv[2][B_][F_];             // 1/(mask sum + eps)
__device__ float d_G[B_][F_][C_][C_][2];        // G[m][c] = conj(W[c][m])

__device__ __forceinline__ float gldf(const float* p, long long i, long long cap) {
    return (i >= 0 && i < cap) ? p[i] : 0.0f;
}
__device__ __forceinline__ float4 gld4(const float* p, long long i, long long cap) {
    if (i >= 0 && i + 3 < cap && ((i & 3) == 0))
        return *(const float4*)(p + i);
    return make_float4(gldf(p, i, cap), gldf(p, i + 1, cap),
                       gldf(p, i + 2, cap), gldf(p, i + 3, cap));
}

// ---- A: mask sums -> reciprocals. one thread per (b,f) ----
__global__ void kA(const float* __restrict__ ms, const float* __restrict__ mn,
                   long long capm) {
    int g = blockIdx.x * blockDim.x + threadIdx.x;
    if (g >= B_ * F_) return;
    int b = g >> 9, f = g & 511;
    long long base = ((long long)b * F_ + f) * T_;
    float ss = 0.f, sn = 0.f;
    for (int t = 0; t < T_; t += 4) {
        float4 a = gld4(ms, base + t, capm);
        float4 c = gld4(mn, base + t, capm);
        ss += a.x + a.y + a.z + a.w;
        sn += c.x + c.y + c.z + c.w;
    }
    d_minv[0][b][f] = 1.0f / (ss + 1e-10f);
    d_minv[1][b][f] = 1.0f / (sn + 1e-10f);
}

// ---- B: masked PSD accumulation. block per (b,f); thread = (s, r, e) ----
__global__ void __launch_bounds__(128)
kB(const float* __restrict__ re, const float* __restrict__ im,
   const float* __restrict__ ms, const float* __restrict__ mn,
   long long caps, long long capm) {
    int bf = blockIdx.x;
    int b = bf >> 9, f = bf & 511;
    int tid = threadIdx.x;              // 0..127
    int s = tid >> 6, r = (tid >> 3) & 7, e = tid & 7;
    const float* mk = (s == 0) ? ms : mn;
    long long mbase = ((long long)b * F_ + f) * T_;
    long long rbase = ((long long)(b * C_ + r) * F_ + f) * T_;
    long long ebase = ((long long)(b * C_ + e) * F_ + f) * T_;
    float ar = 0.f, ai = 0.f;
    for (int t = 0; t < T_; t += 4) {
        float4 m  = gld4(mk, mbase + t, capm);
        float4 xr = gld4(re, rbase + t, caps);
        float4 xi = gld4(im, rbase + t, caps);
        float4 yr = gld4(re, ebase + t, caps);
        float4 yi = gld4(im, ebase + t, caps);
        // x * conj(y), mask-weighted, 4 time steps
        ar = fmaf(m.x, fmaf(xr.x, yr.x,  xi.x * yi.x), ar);
        ai = fmaf(m.x, fmaf(xi.x, yr.x, -xr.x * yi.x), ai);
        ar = fmaf(m.y, fmaf(xr.y, yr.y,  xi.y * yi.y), ar);
        ai = fmaf(m.y, fmaf(xi.y, yr.y, -xr.y * yi.y), ai);
        ar = fmaf(m.z, fmaf(xr.z, yr.z,  xi.z * yi.z), ar);
        ai = fmaf(m.z, fmaf(xi.z, yr.z, -xr.z * yi.z), ai);
        ar = fmaf(m.w, fmaf(xr.w, yr.w,  xi.w * yi.w), ar);
        ai = fmaf(m.w, fmaf(xi.w, yr.w, -xr.w * yi.w), ai);
    }
    d_psd[s][b][f][r][e][0] = ar;
    d_psd[s][b][f][r][e][1] = ai;
}

// ---- C: per-(b,f) 8x8 complex solve + Wiener normalization. 1 thread each ----
__global__ void kC() {
    int g = blockIdx.x * blockDim.x + threadIdx.x;
    if (g >= B_ * F_) return;
    int b = g >> 9, f = g & 511;
    float invS = d_minv[0][b][f], invN = d_minv[1][b][f];

    float Ar[8][8], Ai[8][8], Br[8][8], Bi[8][8];
    float tr = 0.f;
    for (int i = 0; i < 8; i++)
        for (int j = 0; j < 8; j++) {
            Ar[i][j] = d_psd[1][b][f][i][j][0] * invN;
            Ai[i][j] = d_psd[1][b][f][i][j][1] * invN;
            Br[i][j] = d_psd[0][b][f][i][j][0] * invS;
            Bi[i][j] = d_psd[0][b][f][i][j][1] * invS;
            if (i == j) tr += Ar[i][j];
        }
    float d = 1e-6f * tr + 1e-8f;       // DIAG_REG * Re(tr(psd_n)) + EPS
    for (int i = 0; i < 8; i++) Ar[i][i] += d;

    // Gauss-Jordan (HPD + regularization: no pivoting needed), solve A X = B
    for (int k = 0; k < 8; k++) {
        float pr = Ar[k][k], pi = Ai[k][k];
        float pinv = 1.0f / fmaf(pr, pr, pi * pi);
        float qr = pr * pinv, qi = -pi * pinv;          // 1/pivot
        for (int j = 0; j < 8; j++) {
            float tre = Ar[k][j] * qr - Ai[k][j] * qi;
            float tim = Ar[k][j] * qi + Ai[k][j] * qr;
            Ar[k][j] = tre; Ai[k][j] = tim;
            tre = Br[k][j] * qr - Bi[k][j] * qi;
            tim = Br[k][j] * qi + Bi[k][j] * qr;
            Br[k][j] = tre; Bi[k][j] = tim;
        }
        for (int i = 0; i < 8; i++) {
            if (i == k) continue;
            float fr = Ar[i][k], fi = Ai[i][k];
            for (int j = 0; j < 8; j++) {
                Ar[i][j] -= fr * Ar[k][j] - fi * Ai[k][j];
                Ai[i][j] -= fr * Ai[k][j] + fi * Ar[k][j];
                Br[i][j] -= fr * Br[k][j] - fi * Bi[k][j];
                Bi[i][j] -= fr * Bi[k][j] + fi * Br[k][j];
            }
        }
    }
    // denom = beta + tr(X)
    float dr = 1.0f, di = 0.0f;
    for (int i = 0; i < 8; i++) { dr += Br[i][i]; di += Bi[i][i]; }
    float dinv = 1.0f / fmaf(dr, dr, di * di);
    float ir = dr * dinv, ii = -di * dinv;              // 1/denom
    for (int m = 0; m < 8; m++)
        for (int c = 0; c < 8; c++) {
            float wr = Br[c][m] * ir - Bi[c][m] * ii;   // (X/denom)[c][m]
            float wi = Br[c][m] * ii + Bi[c][m] * ir;
            d_G[b][f][m][c][0] = wr;                    // conj -> negate imag
            d_G[b][f][m][c][1] = -wi;
        }
}

// ---- D: apply filter. one thread per (b,f,t). PLANAR output:
//      out[0][b][m][f][t] = Re, out[1][b][m][f][t] = Im  (float32 (2,B,C,F,T)) ----
__global__ void __launch_bounds__(256)
kD(const float* __restrict__ re, const float* __restrict__ im,
   float* __restrict__ outf, long long caps, long long capoutf) {
    long long g = (long long)blockIdx.x * blockDim.x + threadIdx.x;
    if (g >= (long long)B_ * F_ * T_) return;
    int t  = (int)(g % T_);
    int bf = (int)(g / T_);
    int b = bf >> 9, f = bf & 511;

    float xr[8], xi[8];
    for (int c = 0; c < 8; c++) {
        long long base = ((long long)(b * C_ + c) * F_ + f) * T_;
        xr[c] = gldf(re, base + t, caps);
        xi[c] = gldf(im, base + t, caps);
    }
    for (int m = 0; m < 8; m++) {
        float accr = 0.f, acci = 0.f;
        for (int c = 0; c < 8; c++) {
            float gr = d_G[b][f][m][c][0];
            float gi = d_G[b][f][m][c][1];
            accr += gr * xr[c] - gi * xi[c];
            acci += gr * xi[c] + gi * xr[c];
        }
        long long oc = ((long long)(b * C_ + m) * F_ + f) * T_ + t;
        long long or_ = oc;            // real plane
        long long oi_ = SPEC_N + oc;   // imag plane
        if (or_ >= 0 && or_ < capoutf) outf[or_] = accr;
        if (oi_ >= 0 && oi_ < capoutf) outf[oi_] = acci;
    }
}

extern "C" void kernel_launch(void* const* d_in, const int* in_sizes, int n_in,
                              void* d_out, int out_size) {
    if (n_in < 4 || !d_out) return;   // bail cleanly: no work, no crash

    const float* re  = (const float*)d_in[0];
    const float* im  = (const float*)d_in[1];
    const float* mks = (const float*)d_in[2];
    const float* mkn = (const float*)d_in[3];
    long long cap_re = (long long)in_sizes[0];
    long long cap_im = (long long)in_sizes[1];
    long long caps   = cap_re < cap_im ? cap_re : cap_im;
    long long cm0 = (long long)in_sizes[2];
    long long cm1 = (long long)in_sizes[3];
    long long capm = cm0 < cm1 ? cm0 : cm1;

    // out_size counts FLOAT32 elements (confirmed: conservative float guard
    // removed the OOB crash in round 5). Never write beyond it.
    long long capoutf = (long long)out_size;

    kA<<<(B_ * F_ + 255) / 256, 256>>>(mks, mkn, capm);
    kB<<<B_ * F_, 128>>>(re, im, mks, mkn, caps, capm);
    kC<<<(B_ * F_ + 255) / 256, 256>>>();
    long long total = (long long)B_ * F_ * T_;
    kD<<<(unsigned)((total + 255) / 256), 256>>>(re, im, (float*)d_out, caps, capoutf);
}

// round 7
// speedup vs baseline: 1.8483x; 1.8483x over previous
#include <cuda_runtime.h>
#include <cstring>

#define B_ 4
#define C_ 8
#define F_ 512
#define T_ 1000

#define SPEC_N 16384000ll   // B*C*F*T
#define NBF    2048         // B*F

// -------- device scratch (sanctioned alternative to cudaMalloc) --------
// kB per-lane partials: [bf][pm(256)][lane(32)] floats  (pm = ((r*8+e)*2+s)*2+reim)
__device__ __align__(16) float d_part[(size_t)NBF * 256 * 32];
// reduced PSD sums: [bf][pm]
__device__ __align__(16) float d_psdF[(size_t)NBF * 256];
__device__ float d_minv[2][NBF];                       // 1/(mask sum + eps)
// filter: [bf][m][c][2]  (G[m][c] = conj(W[c][m]))
__device__ __align__(16) float d_G[(size_t)NBF * 128];

// ---------------- helpers ----------------
__device__ __forceinline__ float gldf(const float* p, long long i, long long cap) {
    return (i >= 0 && i < cap) ? p[i] : 0.0f;
}
__device__ __forceinline__ float4 gld4(const float* p, long long i, long long cap) {
    if (i >= 0 && i + 3 < cap && ((i & 3) == 0))
        return *(const float4*)(p + i);
    return make_float4(gldf(p, i, cap), gldf(p, i + 1, cap),
                       gldf(p, i + 2, cap), gldf(p, i + 3, cap));
}
__device__ __forceinline__ void gst4(float* p, long long i, long long cap, float4 v) {
    if (i >= 0 && i + 3 < cap && ((i & 3) == 0)) { *(float4*)(p + i) = v; return; }
    if (i >= 0     && i     < cap) p[i]     = v.x;
    if (i + 1 >= 0 && i + 1 < cap) p[i + 1] = v.y;
    if (i + 2 >= 0 && i + 2 < cap) p[i + 2] = v.z;
    if (i + 3 >= 0 && i + 3 < cap) p[i + 3] = v.w;
}

// packed f32x2 (Blackwell): d = a*b + c per 32-bit lane-pair
__device__ __forceinline__ unsigned long long f2u(float2 v) {
    unsigned long long u; memcpy(&u, &v, 8); return u;
}
__device__ __forceinline__ float2 u2f(unsigned long long u) {
    float2 v; memcpy(&v, &u, 8); return v;
}
__device__ __forceinline__ float2 ffma2(float2 a, float2 b, float2 c) {
    unsigned long long r;
    asm("fma.rn.f32x2 %0, %1, %2, %3;" : "=l"(r) : "l"(f2u(a)), "l"(f2u(b)), "l"(f2u(c)));
    return u2f(r);
}
__device__ __forceinline__ float2 fmul2(float2 a, float2 b) {
    unsigned long long r;
    asm("mul.rn.f32x2 %0, %1, %2;" : "=l"(r) : "l"(f2u(a)), "l"(f2u(b)));
    return u2f(r);
}

// ---- A: mask sums -> reciprocals. one thread per (b,f) ----
__global__ void kA(const float* __restrict__ ms, const float* __restrict__ mn,
                   long long capm) {
    int g = blockIdx.x * blockDim.x + threadIdx.x;
    if (g >= NBF) return;
    long long base = (long long)g * T_;
    float ss = 0.f, sn = 0.f;
    for (int t = 0; t < T_; t += 4) {
        float4 a = gld4(ms, base + t, capm);
        float4 c = gld4(mn, base + t, capm);
        ss += a.x + a.y + a.z + a.w;
        sn += c.x + c.y + c.z + c.w;
    }
    d_minv[0][g] = 1.0f / (ss + 1e-10f);
    d_minv[1][g] = 1.0f / (sn + 1e-10f);
}

// ---- B: masked PSD, register-tiled. block per (b,f); thread = (p, lane) ----
// p = warp id (0..7): rp = p>>1 -> rows {rp, rp+4}; ep = p&1 -> e in [4*ep, 4*ep+4)
// lane strides T in float4 groups. Partials -> d_part (no reduction features).
__global__ void __launch_bounds__(256)
kB(const float* __restrict__ re, const float* __restrict__ im,
   const float* __restrict__ ms, const float* __restrict__ mn,
   long long caps, long long capm) {
    const int bf   = blockIdx.x;
    const int b    = bf >> 9, f = bf & 511;
    const int tid  = threadIdx.x;
    const int p    = tid >> 5;
    const int lane = tid & 31;
    const int rp   = p >> 1, ep = p & 1;
    const int r0   = rp, r1 = rp + 4;
    const int e0   = ep * 4;

    const long long mb  = (long long)bf * T_;
    const long long xb0 = ((long long)(b * C_ + r0) * F_ + f) * T_;
    const long long xb1 = ((long long)(b * C_ + r1) * F_ + f) * T_;
    long long yb[4];
    #pragma unroll
    for (int le = 0; le < 4; le++)
        yb[le] = ((long long)(b * C_ + e0 + le) * F_ + f) * T_;

    // acc[lr][le][s] complex
    float2 acc[2][4][2];
    #pragma unroll
    for (int lr = 0; lr < 2; lr++)
        #pragma unroll
        for (int le = 0; le < 4; le++)
            #pragma unroll
            for (int s = 0; s < 2; s++)
                acc[lr][le][s] = make_float2(0.f, 0.f);

    for (int i4 = lane; i4 < T_ / 4; i4 += 32) {
        const int t = i4 * 4;
        float4 m0 = gld4(ms, mb + t, capm);
        float4 m1 = gld4(mn, mb + t, capm);
        float4 xr0 = gld4(re, xb0 + t, caps), xi0 = gld4(im, xb0 + t, caps);
        float4 xr1 = gld4(re, xb1 + t, caps), xi1 = gld4(im, xb1 + t, caps);
        float4 yr[4], yi[4];
        #pragma unroll
        for (int le = 0; le < 4; le++) {
            yr[le] = gld4(re, yb[le] + t, caps);
            yi[le] = gld4(im, yb[le] + t, caps);
        }
        const float* m0a  = &m0.x;  const float* m1a  = &m1.x;
        const float* xr0a = &xr0.x; const float* xi0a = &xi0.x;
        const float* xr1a = &xr1.x; const float* xi1a = &xi1.x;
        #pragma unroll
        for (int j = 0; j < 4; j++) {
            float2 msj = make_float2(m0a[j], m0a[j]);
            float2 mnj = make_float2(m1a[j], m1a[j]);
            // x vectors and their "rotated negatives" for packed complex cross
            float2 x0  = make_float2(xr0a[j], xi0a[j]);
            float2 x0n = make_float2(xi0a[j], -xr0a[j]);
            float2 x1  = make_float2(xr1a[j], xi1a[j]);
            float2 x1n = make_float2(xi1a[j], -xr1a[j]);
            #pragma unroll
            for (int le = 0; le < 4; le++) {
                const float* yra = &yr[le].x; const float* yia = &yi[le].x;
                float2 yrr = make_float2(yra[j], yra[j]);
                float2 yii = make_float2(yia[j], yia[j]);
                // c = x * conj(y) = (xr*yr + xi*yi, xi*yr - xr*yi)
                float2 c0 = ffma2(x0n, yii, fmul2(x0, yrr));
                float2 c1 = ffma2(x1n, yii, fmul2(x1, yrr));
                acc[0][le][0] = ffma2(msj, c0, acc[0][le][0]);
                acc[0][le][1] = ffma2(mnj, c0, acc[0][le][1]);
                acc[1][le][0] = ffma2(msj, c1, acc[1][le][0]);
                acc[1][le][1] = ffma2(mnj, c1, acc[1][le][1]);
            }
        }
    }

    // write partials: d_part[bf][pm][lane], pm = ((r*8+e)*2+s)*2+reim
    #pragma unroll
    for (int lr = 0; lr < 2; lr++) {
        const int r = (lr == 0) ? r0 : r1;
        #pragma unroll
        for (int le = 0; le < 4; le++) {
            const int e = e0 + le;
            #pragma unroll
            for (int s = 0; s < 2; s++) {
                size_t pm = (size_t)((r * 8 + e) * 2 + s) * 2;
                size_t base = ((size_t)bf * 256 + pm) * 32 + lane;
                d_part[base]      = acc[lr][le][s].x;
                d_part[base + 32] = acc[lr][le][s].y;
            }
        }
    }
}

// ---- R: reduce 32 lane-partials per (bf, pm) ----
__global__ void __launch_bounds__(256)
kR() {
    size_t g = (size_t)blockIdx.x * blockDim.x + threadIdx.x;
    if (g >= (size_t)NBF * 256) return;
    const float4* q = (const float4*)(d_part + g * 32);
    float s = 0.f;
    #pragma unroll
    for (int k = 0; k < 8; k++) {
        float4 v = q[k];
        s += (v.x + v.y) + (v.z + v.w);
    }
    d_psdF[g] = s;
}

// ---- C: per-(b,f) 8x8 complex solve + Wiener normalization. 1 thread each ----
__global__ void kC() {
    int g = blockIdx.x * blockDim.x + threadIdx.x;
    if (g >= NBF) return;
    const float invS = d_minv[0][g], invN = d_minv[1][g];
    const float* P = d_psdF + (size_t)g * 256;

    float Ar[8][8], Ai[8][8], Br[8][8], Bi[8][8];
    float tr = 0.f;
    for (int i = 0; i < 8; i++)
        for (int j = 0; j < 8; j++) {
            int pe = (i * 8 + j) * 2;
            Br[i][j] = P[(pe + 0) * 2 + 0] * invS;   // psd_s
            Bi[i][j] = P[(pe + 0) * 2 + 1] * invS;
            Ar[i][j] = P[(pe + 1) * 2 + 0] * invN;   // psd_n
            Ai[i][j] = P[(pe + 1) * 2 + 1] * invN;
            if (i == j) tr += Ar[i][j];
        }
    float d = 1e-6f * tr + 1e-8f;       // DIAG_REG * Re(tr(psd_n)) + EPS
    for (int i = 0; i < 8; i++) Ar[i][i] += d;

    // Gauss-Jordan, solve A X = B  (HPD + reg -> no pivoting)
    for (int k = 0; k < 8; k++) {
        float pr = Ar[k][k], pi = Ai[k][k];
        float pinv = 1.0f / fmaf(pr, pr, pi * pi);
        float qr = pr * pinv, qi = -pi * pinv;
        for (int j = 0; j < 8; j++) {
            float tre = Ar[k][j] * qr - Ai[k][j] * qi;
            float tim = Ar[k][j] * qi + Ai[k][j] * qr;
            Ar[k][j] = tre; Ai[k][j] = tim;
            tre = Br[k][j] * qr - Bi[k][j] * qi;
            tim = Br[k][j] * qi + Bi[k][j] * qr;
            Br[k][j] = tre; Bi[k][j] = tim;
        }
        for (int i = 0; i < 8; i++) {
            if (i == k) continue;
            float fr = Ar[i][k], fi = Ai[i][k];
            for (int j = 0; j < 8; j++) {
                Ar[i][j] -= fr * Ar[k][j] - fi * Ai[k][j];
                Ai[i][j] -= fr * Ai[k][j] + fi * Ar[k][j];
                Br[i][j] -= fr * Br[k][j] - fi * Bi[k][j];
                Bi[i][j] -= fr * Bi[k][j] + fi * Br[k][j];
            }
        }
    }
    // denom = beta + tr(X);  G[m][c] = conj(X[c][m] / denom)
    float dr = 1.0f, di = 0.0f;
    for (int i = 0; i < 8; i++) { dr += Br[i][i]; di += Bi[i][i]; }
    float dinv = 1.0f / fmaf(dr, dr, di * di);
    float ir = dr * dinv, ii = -di * dinv;
    float* Gp = d_G + (size_t)g * 128;
    for (int m = 0; m < 8; m++)
        for (int c = 0; c < 8; c++) {
            float wr = Br[c][m] * ir - Bi[c][m] * ii;
            float wi = Br[c][m] * ii + Bi[c][m] * ir;
            Gp[(m * 8 + c) * 2 + 0] = wr;
            Gp[(m * 8 + c) * 2 + 1] = -wi;
        }
}

// ---- D: apply filter, thread per (bf, 4t). PLANAR float32 (2,B,C,F,T) out ----
__global__ void __launch_bounds__(256)
kD(const float* __restrict__ re, const float* __restrict__ im,
   float* __restrict__ outf, long long caps, long long capoutf) {
    int g = blockIdx.x * blockDim.x + threadIdx.x;
    const int NG = NBF * (T_ / 4);      // 512000
    if (g >= NG) return;
    const int bf = g / (T_ / 4);
    const int i4 = g - bf * (T_ / 4);
    const int t  = i4 * 4;
    const int b  = bf >> 9, f = bf & 511;

    float4 xr[8], xi[8];
    #pragma unroll
    for (int c = 0; c < 8; c++) {
        long long base = ((long long)(b * C_ + c) * F_ + f) * T_;
        xr[c] = gld4(re, base + t, caps);
        xi[c] = gld4(im, base + t, caps);
    }

    const float4* G4 = (const float4*)(d_G + (size_t)bf * 128);
    #pragma unroll
    for (int m = 0; m < 8; m++) {
        // acc[j] = (re, im) for sub-t j
        float2 a0 = make_float2(0.f, 0.f), a1 = a0, a2 = a0, a3 = a0;
        #pragma unroll
        for (int cc = 0; cc < 4; cc++) {           // 2 channels per float4
            float4 gv = G4[m * 4 + cc];
            float2 g0p = make_float2(gv.x, gv.x);  // (gr,gr) ch c=2cc
            float2 g0n = make_float2(-gv.y, gv.y); // (-gi,gi)
            float2 g1p = make_float2(gv.z, gv.z);  // ch c=2cc+1
            float2 g1n = make_float2(-gv.w, gv.w);
            int c0 = 2 * cc, c1 = 2 * cc + 1;
            const float* xr0 = &xr[c0].x; const float* xi0 = &xi[c0].x;
            const float* xr1 = &xr[c1].x; const float* xi1 = &xi[c1].x;
            a0 = ffma2(g0p, make_float2(xr0[0], xi0[0]), a0);
            a0 = ffma2(g0n, make_float2(xi0[0], xr0[0]), a0);
            a0 = ffma2(g1p, make_float2(xr1[0], xi1[0]), a0);
            a0 = ffma2(g1n, make_float2(xi1[0], xr1[0]), a0);
            a1 = ffma2(g0p, make_float2(xr0[1], xi0[1]), a1);
            a1 = ffma2(g0n, make_float2(xi0[1], xr0[1]), a1);
            a1 = ffma2(g1p, make_float2(xr1[1], xi1[1]), a1);
            a1 = ffma2(g1n, make_float2(xi1[1], xr1[1]), a1);
            a2 = ffma2(g0p, make_float2(xr0[2], xi0[2]), a2);
            a2 = ffma2(g0n, make_float2(xi0[2], xr0[2]), a2);
            a2 = ffma2(g1p, make_float2(xr1[2], xi1[2]), a2);
            a2 = ffma2(g1n, make_float2(xi1[2], xr1[2]), a2);
            a3 = ffma2(g0p, make_float2(xr0[3], xi0[3]), a3);
            a3 = ffma2(g0n, make_float2(xi0[3], xr0[3]), a3);
            a3 = ffma2(g1p, make_float2(xr1[3], xi1[3]), a3);
            a3 = ffma2(g1n, make_float2(xi1[3], xr1[3]), a3);
        }
        long long oc = ((long long)(b * C_ + m) * F_ + f) * T_ + t;
        gst4(outf, oc,          capoutf, make_float4(a0.x, a1.x, a2.x, a3.x));  // real plane
        gst4(outf, SPEC_N + oc, capoutf, make_float4(a0.y, a1.y, a2.y, a3.y));  // imag plane
    }
}

extern "C" void kernel_launch(void* const* d_in, const int* in_sizes, int n_in,
                              void* d_out, int out_size) {
    if (n_in < 4 || !d_out) return;

    const float* re  = (const float*)d_in[0];
    const float* im  = (const float*)d_in[1];
    const float* mks = (const float*)d_in[2];
    const float* mkn = (const float*)d_in[3];
    long long cap_re = (long long)in_sizes[0];
    long long cap_im = (long long)in_sizes[1];
    long long caps   = cap_re < cap_im ? cap_re : cap_im;
    long long cm0 = (long long)in_sizes[2];
    long long cm1 = (long long)in_sizes[3];
    long long capm = cm0 < cm1 ? cm0 : cm1;
    long long capoutf = (long long)out_size;   // float32 element count (confirmed)

    kA<<<(NBF + 255) / 256, 256>>>(mks, mkn, capm);
    kB<<<NBF, 256>>>(re, im, mks, mkn, caps, capm);
    kR<<<(NBF * 256 + 255) / 256, 256>>>();
    kC<<<(NBF + 255) / 256, 256>>>();
    kD<<<(NBF * (T_ / 4) + 255) / 256, 256>>>(re, im, (float*)d_out, caps, capoutf);
}

// round 8
// speedup vs baseline: 2.5217x; 1.3643x over previous
#include <cuda_runtime.h>
#include <cstring>

#define B_ 4
#define C_ 8
#define F_ 512
#define T_ 1000

#define SPEC_N 16384000ll   // B*C*F*T
#define NBF    2048         // B*F

// triangle pair index for r <= e
#define IDX(r, e) ((r) * 8 + (e) - ((r) * ((r) + 1)) / 2)   // 0..35

// -------- device scratch (sanctioned alternative to cudaMalloc) --------
// kB partials: [bf][p36][q4][64]   q: 0=S.re 1=S.im 2=N.re 3=N.im ; 64 = half*32+lane
__device__ __align__(16) float d_part[(size_t)NBF * 36 * 4 * 64];
__device__ float d_minv[2][NBF];                        // 1/(mask sum + eps)
__device__ __align__(16) float d_G[(size_t)NBF * 128];  // [bf][m][c][2] : conj(W[c][m])

// ---------------- helpers ----------------
__device__ __forceinline__ float gldf(const float* p, long long i, long long cap) {
    return (i >= 0 && i < cap) ? p[i] : 0.0f;
}
__device__ __forceinline__ float4 gld4(const float* p, long long i, long long cap) {
    if (i >= 0 && i + 3 < cap && ((i & 3) == 0))
        return *(const float4*)(p + i);
    return make_float4(gldf(p, i, cap), gldf(p, i + 1, cap),
                       gldf(p, i + 2, cap), gldf(p, i + 3, cap));
}
__device__ __forceinline__ void gst4(float* p, long long i, long long cap, float4 v) {
    if (i >= 0 && i + 3 < cap && ((i & 3) == 0)) { *(float4*)(p + i) = v; return; }
    if (i >= 0     && i     < cap) p[i]     = v.x;
    if (i + 1 >= 0 && i + 1 < cap) p[i + 1] = v.y;
    if (i + 2 >= 0 && i + 2 < cap) p[i + 2] = v.z;
    if (i + 3 >= 0 && i + 3 < cap) p[i + 3] = v.w;
}
__device__ __forceinline__ unsigned long long f2u(float2 v) {
    unsigned long long u; memcpy(&u, &v, 8); return u;
}
__device__ __forceinline__ float2 u2f(unsigned long long u) {
    float2 v; memcpy(&v, &u, 8); return v;
}
__device__ __forceinline__ float2 ffma2(float2 a, float2 b, float2 c) {
    unsigned long long r;
    asm("fma.rn.f32x2 %0, %1, %2, %3;" : "=l"(r) : "l"(f2u(a)), "l"(f2u(b)), "l"(f2u(c)));
    return u2f(r);
}
__device__ __forceinline__ float2 fmul2(float2 a, float2 b) {
    unsigned long long r;
    asm("mul.rn.f32x2 %0, %1, %2;" : "=l"(r) : "l"(f2u(a)), "l"(f2u(b)));
    return u2f(r);
}
__device__ __forceinline__ float2 cmul(float2 a, float2 b) {
    return make_float2(fmaf(a.x, b.x, -a.y * b.y), fmaf(a.x, b.y, a.y * b.x));
}
__device__ __forceinline__ float2 crecip(float2 a) {
    float inv = 1.0f / fmaf(a.x, a.x, a.y * a.y);
    return make_float2(a.x * inv, -a.y * inv);
}

// ---- A: mask sums -> reciprocals. one thread per (b,f) ----
__global__ void kA(const float* __restrict__ ms, const float* __restrict__ mn,
                   long long capm) {
    int g = blockIdx.x * blockDim.x + threadIdx.x;
    if (g >= NBF) return;
    long long base = (long long)g * T_;
    float ss = 0.f, sn = 0.f;
    for (int t = 0; t < T_; t += 4) {
        float4 a = gld4(ms, base + t, capm);
        float4 c = gld4(mn, base + t, capm);
        ss += a.x + a.y + a.z + a.w;
        sn += c.x + c.y + c.z + c.w;
    }
    d_minv[0][g] = 1.0f / (ss + 1e-10f);
    d_minv[1][g] = 1.0f / (sn + 1e-10f);
}

// ---- B: masked PSD, upper triangle only. block=(bf, rq) 64 thr = 2 T-halves ----
template<int RQ>
__device__ __forceinline__ void kB_body(
    int bf, int half, int lane,
    const float* __restrict__ re, const float* __restrict__ im,
    const float* __restrict__ ms, const float* __restrict__ mn,
    long long caps, long long capm)
{
    constexpr int R1 = 7 - RQ;
    const int b = bf >> 9, f = bf & 511;
    const long long mb = (long long)bf * T_;
    long long xb[8];
    #pragma unroll
    for (int q = RQ; q < 8; q++)
        xb[q] = ((long long)(b * C_ + q) * F_ + f) * T_;

    float2 a0S[8], a0N[8], a1S[8], a1N[8];
    #pragma unroll
    for (int e = RQ; e < 8; e++) { a0S[e] = make_float2(0.f, 0.f); a0N[e] = a0S[e]; }
    #pragma unroll
    for (int e = R1; e < 8; e++) { a1S[e] = make_float2(0.f, 0.f); a1N[e] = a1S[e]; }

    const int i4beg = half * (T_ / 8) + lane;   // halves of 250 i4-groups
    const int i4end = half ? (T_ / 4) : (T_ / 8);
    for (int i4 = i4beg; i4 < i4end; i4 += 32) {
        const int t = i4 * 4;
        float4 mS4 = gld4(ms, mb + t, capm);
        float4 mN4 = gld4(mn, mb + t, capm);
        float4 yr[8], yi[8];
        #pragma unroll
        for (int q = RQ; q < 8; q++) {
            yr[q] = gld4(re, xb[q] + t, caps);
            yi[q] = gld4(im, xb[q] + t, caps);
        }
        const float* mSa = &mS4.x; const float* mNa = &mN4.x;
        #pragma unroll
        for (int j = 0; j < 4; j++) {
            float2 mS2 = make_float2(mSa[j], mSa[j]);
            float2 mN2 = make_float2(mNa[j], mNa[j]);
            {   // row RQ vs e = RQ..7
                float xr0 = (&yr[RQ].x)[j], xi0 = (&yi[RQ].x)[j];
                float2 x0  = make_float2(xr0, xi0);
                float2 x0n = make_float2(xi0, -xr0);
                #pragma unroll
                for (int e = RQ; e < 8; e++) {
                    float yre = (&yr[e].x)[j], yie = (&yi[e].x)[j];
                    float2 c = ffma2(x0n, make_float2(yie, yie),
                                     fmul2(x0, make_float2(yre, yre)));
                    a0S[e] = ffma2(mS2, c, a0S[e]);
                    a0N[e] = ffma2(mN2, c, a0N[e]);
                }
            }
            {   // row R1 vs e = R1..7
                float xr1 = (&yr[R1].x)[j], xi1 = (&yi[R1].x)[j];
                float2 x1  = make_float2(xr1, xi1);
                float2 x1n = make_float2(xi1, -xr1);
                #pragma unroll
                for (int e = R1; e < 8; e++) {
                    float yre = (&yr[e].x)[j], yie = (&yi[e].x)[j];
                    float2 c = ffma2(x1n, make_float2(yie, yie),
                                     fmul2(x1, make_float2(yre, yre)));
                    a1S[e] = ffma2(mS2, c, a1S[e]);
                    a1N[e] = ffma2(mN2, c, a1N[e]);
                }
            }
        }
    }

    // write partials: [bf][p][q][half*32+lane]
    #pragma unroll
    for (int e = RQ; e < 8; e++) {
        size_t base = ((size_t)bf * 36 + IDX(RQ, e)) * 256 + half * 32 + lane;
        d_part[base +   0] = a0S[e].x;
        d_part[base +  64] = a0S[e].y;
        d_part[base + 128] = a0N[e].x;
        d_part[base + 192] = a0N[e].y;
    }
    #pragma unroll
    for (int e = R1; e < 8; e++) {
        size_t base = ((size_t)bf * 36 + IDX(R1, e)) * 256 + half * 32 + lane;
        d_part[base +   0] = a1S[e].x;
        d_part[base +  64] = a1S[e].y;
        d_part[base + 128] = a1N[e].x;
        d_part[base + 192] = a1N[e].y;
    }
}

__global__ void __launch_bounds__(64)
kB(const float* __restrict__ re, const float* __restrict__ im,
   const float* __restrict__ ms, const float* __restrict__ mn,
   long long caps, long long capm) {
    const int bf   = blockIdx.x;
    const int rq   = blockIdx.y;
    const int half = threadIdx.x >> 5;
    const int lane = threadIdx.x & 31;
    switch (rq) {
        case 0: kB_body<0>(bf, half, lane, re, im, ms, mn, caps, capm); break;
        case 1: kB_body<1>(bf, half, lane, re, im, ms, mn, caps, capm); break;
        case 2: kB_body<2>(bf, half, lane, re, im, ms, mn, caps, capm); break;
        default: kB_body<3>(bf, half, lane, re, im, ms, mn, caps, capm); break;
    }
}

// ---- C: fused reduce + warp-parallel Gauss-Jordan. one warp per (b,f) ----
__global__ void __launch_bounds__(256)
kC() {
    const int w    = blockIdx.x * 8 + (threadIdx.x >> 5);   // bf, grid 256 -> 2048
    const int lane = threadIdx.x & 31;
    const float invS = d_minv[0][w];
    const float invN = d_minv[1][w];

    float2 col[8];          // lane j<8: column j of A (psd_n); 8..15: column of B (psd_s)
    #pragma unroll
    for (int i = 0; i < 8; i++) col[i] = make_float2(0.f, 0.f);
    float trN = 0.f;

    #pragma unroll
    for (int r = 0; r < 8; r++) {
        #pragma unroll
        for (int e = r; e < 8; e++) {
            size_t base = ((size_t)w * 36 + IDX(r, e)) * 256;
            float v[4];
            #pragma unroll
            for (int q = 0; q < 4; q++) {
                float s = d_part[base + q * 64 + lane] + d_part[base + q * 64 + 32 + lane];
                #pragma unroll
                for (int o = 16; o; o >>= 1)
                    s += __shfl_xor_sync(0xffffffffu, s, o);
                v[q] = s;
            }
            float Sre = v[0] * invS, Sim = v[1] * invS;
            float Nre = v[2] * invN, Nim = v[3] * invN;
            if (r == e) trN += Nre;
            if (lane == e)              col[r] = make_float2(Nre,  Nim);
            if (lane == r && r != e)    col[e] = make_float2(Nre, -Nim);
            if (lane == 8 + e)          col[r] = make_float2(Sre,  Sim);
            if (lane == 8 + r && r != e) col[e] = make_float2(Sre, -Sim);
        }
    }
    // diagonal regularization on A (lanes 0..7)
    const float d = 1e-6f * trN + 1e-8f;
    #pragma unroll
    for (int i = 0; i < 8; i++)
        if (lane == i) col[i].x += d;

    // Gauss-Jordan on [A | B] (no pivoting: HPD + reg)
    #pragma unroll
    for (int k = 0; k < 8; k++) {
        float2 piv;
        piv.x = __shfl_sync(0xffffffffu, col[k].x, k);
        piv.y = __shfl_sync(0xffffffffu, col[k].y, k);
        float2 pinv = crecip(piv);
        col[k] = cmul(col[k], pinv);
        #pragma unroll
        for (int i = 0; i < 8; i++) {
            if (i == k) continue;
            float2 fct;
            fct.x = __shfl_sync(0xffffffffu, col[i].x, k);
            fct.y = __shfl_sync(0xffffffffu, col[i].y, k);
            float2 t2 = cmul(fct, col[k]);
            col[i].x -= t2.x; col[i].y -= t2.y;
        }
    }

    // trace of X (held by lanes 8..15: lane 8+i has col[i] = X[i][i])
    float2 dg = make_float2(0.f, 0.f);
    #pragma unroll
    for (int i = 0; i < 8; i++)
        if (lane == 8 + i) dg = col[i];
    #pragma unroll
    for (int o = 16; o; o >>= 1) {
        dg.x += __shfl_xor_sync(0xffffffffu, dg.x, o);
        dg.y += __shfl_xor_sync(0xffffffffu, dg.y, o);
    }
    float2 cd = make_float2(1.0f + dg.x, -dg.y);   // conj(beta + tr(X))
    float2 E  = crecip(cd);                        // 1 / conj(denom)

    // G[m][c] = conj(X[c][m]) * E ; lane 8+m holds col[c] = X[c][m]
    if (lane >= 8 && lane < 16) {
        const int m = lane - 8;
        float2* Gp = (float2*)(d_G + (size_t)w * 128) + m * 8;
        #pragma unroll
        for (int c = 0; c < 8; c++) {
            float2 xc = make_float2(col[c].x, -col[c].y);
            Gp[c] = cmul(xc, E);
        }
    }
}

// ---- D: apply filter, thread per (bf, 4t). PLANAR float32 (2,B,C,F,T) out ----
__global__ void __launch_bounds__(256)
kD(const float* __restrict__ re, const float* __restrict__ im,
   float* __restrict__ outf, long long caps, long long capoutf) {
    int g = blockIdx.x * blockDim.x + threadIdx.x;
    const int NG = NBF * (T_ / 4);      // 512000
    if (g >= NG) return;
    const int bf = g / (T_ / 4);
    const int i4 = g - bf * (T_ / 4);
    const int t  = i4 * 4;
    const int b  = bf >> 9, f = bf & 511;

    float4 xr[8], xi[8];
    #pragma unroll
    for (int c = 0; c < 8; c++) {
        long long base = ((long long)(b * C_ + c) * F_ + f) * T_;
        xr[c] = gld4(re, base + t, caps);
        xi[c] = gld4(im, base + t, caps);
    }

    const float4* G4 = (const float4*)(d_G + (size_t)bf * 128);
    #pragma unroll
    for (int m = 0; m < 8; m++) {
        float2 a0 = make_float2(0.f, 0.f), a1 = a0, a2 = a0, a3 = a0;
        #pragma unroll
        for (int cc = 0; cc < 4; cc++) {
            float4 gv = G4[m * 4 + cc];
            float2 g0p = make_float2(gv.x, gv.x);
            float2 g0n = make_float2(-gv.y, gv.y);
            float2 g1p = make_float2(gv.z, gv.z);
            float2 g1n = make_float2(-gv.w, gv.w);
            int c0 = 2 * cc, c1 = 2 * cc + 1;
            const float* xr0 = &xr[c0].x; const float* xi0 = &xi[c0].x;
            const float* xr1 = &xr[c1].x; const float* xi1 = &xi[c1].x;
            a0 = ffma2(g0p, make_float2(xr0[0], xi0[0]), a0);
            a0 = ffma2(g0n, make_float2(xi0[0], xr0[0]), a0);
            a0 = ffma2(g1p, make_float2(xr1[0], xi1[0]), a0);
            a0 = ffma2(g1n, make_float2(xi1[0], xr1[0]), a0);
            a1 = ffma2(g0p, make_float2(xr0[1], xi0[1]), a1);
            a1 = ffma2(g0n, make_float2(xi0[1], xr0[1]), a1);
            a1 = ffma2(g1p, make_float2(xr1[1], xi1[1]), a1);
            a1 = ffma2(g1n, make_float2(xi1[1], xr1[1]), a1);
            a2 = ffma2(g0p, make_float2(xr0[2], xi0[2]), a2);
            a2 = ffma2(g0n, make_float2(xi0[2], xr0[2]), a2);
            a2 = ffma2(g1p, make_float2(xr1[2], xi1[2]), a2);
            a2 = ffma2(g1n, make_float2(xi1[2], xr1[2]), a2);
            a3 = ffma2(g0p, make_float2(xr0[3], xi0[3]), a3);
            a3 = ffma2(g0n, make_float2(xi0[3], xr0[3]), a3);
            a3 = ffma2(g1p, make_float2(xr1[3], xi1[3]), a3);
            a3 = ffma2(g1n, make_float2(xi1[3], xr1[3]), a3);
        }
        long long oc = ((long long)(b * C_ + m) * F_ + f) * T_ + t;
        gst4(outf, oc,          capoutf, make_float4(a0.x, a1.x, a2.x, a3.x));
        gst4(outf, SPEC_N + oc, capoutf, make_float4(a0.y, a1.y, a2.y, a3.y));
    }
}

extern "C" void kernel_launch(void* const* d_in, const int* in_sizes, int n_in,
                              void* d_out, int out_size) {
    if (n_in < 4 || !d_out) return;

    const float* re  = (const float*)d_in[0];
    const float* im  = (const float*)d_in[1];
    const float* mks = (const float*)d_in[2];
    const float* mkn = (const float*)d_in[3];
    long long cap_re = (long long)in_sizes[0];
    long long cap_im = (long long)in_sizes[1];
    long long caps   = cap_re < cap_im ? cap_re : cap_im;
    long long cm0 = (long long)in_sizes[2];
    long long cm1 = (long long)in_sizes[3];
    long long capm = cm0 < cm1 ? cm0 : cm1;
    long long capoutf = (long long)out_size;   // float32 element count (confirmed)

    kA<<<(NBF + 255) / 256, 256>>>(mks, mkn, capm);
    kB<<<dim3(NBF, 4), 64>>>(re, im, mks, mkn, caps, capm);
    kC<<<NBF / 8, 256>>>();
    kD<<<(NBF * (T_ / 4) + 255) / 256, 256>>>(re, im, (float*)d_out, caps, capoutf);
}

// round 9
// speedup vs baseline: 2.7177x; 1.0777x over previous
#include <cuda_runtime.h>
#include <cstring>

#define B_ 4
#define C_ 8
#define F_ 512
#define T_ 1000

#define SPEC_N 16384000ll   // B*C*F*T
#define NBF    2048         // B*F

// triangle pair index for r <= e
#define IDX(r, e) ((r) * 8 + (e) - ((r) * ((r) + 1)) / 2)   // 0..35

// -------- device scratch (sanctioned alternative to cudaMalloc) --------
// kB partials: [bf][p36][q4][64]   q: 0=S.re 1=S.im 2=N.re 3=N.im ; 64 = half*32+lane
__device__ __align__(16) float d_part[(size_t)NBF * 36 * 4 * 64];
__device__ float d_minv[2][NBF];                        // 1/(mask sum + eps)
__device__ __align__(16) float d_G[(size_t)NBF * 128];  // [bf][m][c][2] : conj(W[c][m])

// ---------------- helpers ----------------
__device__ __forceinline__ float gldf(const float* p, long long i, long long cap) {
    return (i >= 0 && i < cap) ? p[i] : 0.0f;
}
__device__ __forceinline__ float2 gld2(const float* p, long long i, long long cap) {
    if (i >= 0 && i + 1 < cap && ((i & 1) == 0))
        return *(const float2*)(p + i);
    return make_float2(gldf(p, i, cap), gldf(p, i + 1, cap));
}
__device__ __forceinline__ float4 gld4(const float* p, long long i, long long cap) {
    if (i >= 0 && i + 3 < cap && ((i & 3) == 0))
        return *(const float4*)(p + i);
    return make_float4(gldf(p, i, cap), gldf(p, i + 1, cap),
                       gldf(p, i + 2, cap), gldf(p, i + 3, cap));
}
__device__ __forceinline__ void gst2(float* p, long long i, long long cap, float2 v) {
    if (i >= 0 && i + 1 < cap && ((i & 1) == 0)) { *(float2*)(p + i) = v; return; }
    if (i >= 0     && i     < cap) p[i]     = v.x;
    if (i + 1 >= 0 && i + 1 < cap) p[i + 1] = v.y;
}
__device__ __forceinline__ unsigned long long f2u(float2 v) {
    unsigned long long u; memcpy(&u, &v, 8); return u;
}
__device__ __forceinline__ float2 u2f(unsigned long long u) {
    float2 v; memcpy(&v, &u, 8); return v;
}
__device__ __forceinline__ float2 ffma2(float2 a, float2 b, float2 c) {
    unsigned long long r;
    asm("fma.rn.f32x2 %0, %1, %2, %3;" : "=l"(r) : "l"(f2u(a)), "l"(f2u(b)), "l"(f2u(c)));
    return u2f(r);
}
__device__ __forceinline__ float2 fmul2(float2 a, float2 b) {
    unsigned long long r;
    asm("mul.rn.f32x2 %0, %1, %2;" : "=l"(r) : "l"(f2u(a)), "l"(f2u(b)));
    return u2f(r);
}
__device__ __forceinline__ float2 cmul(float2 a, float2 b) {
    return make_float2(fmaf(a.x, b.x, -a.y * b.y), fmaf(a.x, b.y, a.y * b.x));
}
__device__ __forceinline__ float2 crecip(float2 a) {
    float inv = 1.0f / fmaf(a.x, a.x, a.y * a.y);
    return make_float2(a.x * inv, -a.y * inv);
}

// ---- A: mask sums -> reciprocals. one thread per (b,f) ----
__global__ void kA(const float* __restrict__ ms, const float* __restrict__ mn,
                   long long capm) {
    int g = blockIdx.x * blockDim.x + threadIdx.x;
    if (g >= NBF) return;
    long long base = (long long)g * T_;
    float ss = 0.f, sn = 0.f;
    for (int t = 0; t < T_; t += 4) {
        float4 a = gld4(ms, base + t, capm);
        float4 c = gld4(mn, base + t, capm);
        ss += a.x + a.y + a.z + a.w;
        sn += c.x + c.y + c.z + c.w;
    }
    d_minv[0][g] = 1.0f / (ss + 1e-10f);
    d_minv[1][g] = 1.0f / (sn + 1e-10f);
}

// ---- B: masked PSD, upper triangle only. block=(bf, rq) 64 thr = 2 T-halves ----
template<int RQ>
__device__ __forceinline__ void kB_body(
    int bf, int half, int lane,
    const float* __restrict__ re, const float* __restrict__ im,
    const float* __restrict__ ms, const float* __restrict__ mn,
    long long caps, long long capm)
{
    constexpr int R1 = 7 - RQ;
    const int b = bf >> 9, f = bf & 511;
    const long long mb = (long long)bf * T_;
    long long xb[8];
    #pragma unroll
    for (int q = RQ; q < 8; q++)
        xb[q] = ((long long)(b * C_ + q) * F_ + f) * T_;

    float2 a0S[8], a0N[8], a1S[8], a1N[8];
    #pragma unroll
    for (int e = RQ; e < 8; e++) { a0S[e] = make_float2(0.f, 0.f); a0N[e] = a0S[e]; }
    #pragma unroll
    for (int e = R1; e < 8; e++) { a1S[e] = make_float2(0.f, 0.f); a1N[e] = a1S[e]; }

    const int i4beg = half * (T_ / 8) + lane;   // halves of 250 i4-groups
    const int i4end = half ? (T_ / 4) : (T_ / 8);
    for (int i4 = i4beg; i4 < i4end; i4 += 32) {
        const int t = i4 * 4;
        float4 mS4 = gld4(ms, mb + t, capm);
        float4 mN4 = gld4(mn, mb + t, capm);
        float4 yr[8], yi[8];
        #pragma unroll
        for (int q = RQ; q < 8; q++) {
            yr[q] = gld4(re, xb[q] + t, caps);
            yi[q] = gld4(im, xb[q] + t, caps);
        }
        const float* mSa = &mS4.x; const float* mNa = &mN4.x;
        #pragma unroll
        for (int j = 0; j < 4; j++) {
            float2 mS2 = make_float2(mSa[j], mSa[j]);
            float2 mN2 = make_float2(mNa[j], mNa[j]);
            {   // row RQ vs e = RQ..7
                float xr0 = (&yr[RQ].x)[j], xi0 = (&yi[RQ].x)[j];
                float2 x0  = make_float2(xr0, xi0);
                float2 x0n = make_float2(xi0, -xr0);
                #pragma unroll
                for (int e = RQ; e < 8; e++) {
                    float yre = (&yr[e].x)[j], yie = (&yi[e].x)[j];
                    float2 c = ffma2(x0n, make_float2(yie, yie),
                                     fmul2(x0, make_float2(yre, yre)));
                    a0S[e] = ffma2(mS2, c, a0S[e]);
                    a0N[e] = ffma2(mN2, c, a0N[e]);
                }
            }
            {   // row R1 vs e = R1..7
                float xr1 = (&yr[R1].x)[j], xi1 = (&yi[R1].x)[j];
                float2 x1  = make_float2(xr1, xi1);
                float2 x1n = make_float2(xi1, -xr1);
                #pragma unroll
                for (int e = R1; e < 8; e++) {
                    float yre = (&yr[e].x)[j], yie = (&yi[e].x)[j];
                    float2 c = ffma2(x1n, make_float2(yie, yie),
                                     fmul2(x1, make_float2(yre, yre)));
                    a1S[e] = ffma2(mS2, c, a1S[e]);
                    a1N[e] = ffma2(mN2, c, a1N[e]);
                }
            }
        }
    }

    // write partials: [bf][p][q][half*32+lane]
    #pragma unroll
    for (int e = RQ; e < 8; e++) {
        size_t base = ((size_t)bf * 36 + IDX(RQ, e)) * 256 + half * 32 + lane;
        d_part[base +   0] = a0S[e].x;
        d_part[base +  64] = a0S[e].y;
        d_part[base + 128] = a0N[e].x;
        d_part[base + 192] = a0N[e].y;
    }
    #pragma unroll
    for (int e = R1; e < 8; e++) {
        size_t base = ((size_t)bf * 36 + IDX(R1, e)) * 256 + half * 32 + lane;
        d_part[base +   0] = a1S[e].x;
        d_part[base +  64] = a1S[e].y;
        d_part[base + 128] = a1N[e].x;
        d_part[base + 192] = a1N[e].y;
    }
}

__global__ void __launch_bounds__(64)
kB(const float* __restrict__ re, const float* __restrict__ im,
   const float* __restrict__ ms, const float* __restrict__ mn,
   long long caps, long long capm) {
    const int bf   = blockIdx.x;
    const int rq   = blockIdx.y;
    const int half = threadIdx.x >> 5;
    const int lane = threadIdx.x & 31;
    switch (rq) {
        case 0: kB_body<0>(bf, half, lane, re, im, ms, mn, caps, capm); break;
        case 1: kB_body<1>(bf, half, lane, re, im, ms, mn, caps, capm); break;
        case 2: kB_body<2>(bf, half, lane, re, im, ms, mn, caps, capm); break;
        default: kB_body<3>(bf, half, lane, re, im, ms, mn, caps, capm); break;
    }
}

// ---- C: fused reduce + warp-parallel Gauss-Jordan. one warp per (b,f) ----
__global__ void __launch_bounds__(256)
kC() {
    const int w    = blockIdx.x * 8 + (threadIdx.x >> 5);   // bf
    const int lane = threadIdx.x & 31;
    const float invS = d_minv[0][w];
    const float invN = d_minv[1][w];

    float2 col[8];          // lane j<8: column j of A (psd_n); 8..15: column of B (psd_s)
    #pragma unroll
    for (int i = 0; i < 8; i++) col[i] = make_float2(0.f, 0.f);
    float trN = 0.f;

    #pragma unroll
    for (int r = 0; r < 8; r++) {
        #pragma unroll
        for (int e = r; e < 8; e++) {
            size_t base = ((size_t)w * 36 + IDX(r, e)) * 256;
            float v[4];
            #pragma unroll
            for (int q = 0; q < 4; q++) {
                float s = d_part[base + q * 64 + lane] + d_part[base + q * 64 + 32 + lane];
                #pragma unroll
                for (int o = 16; o; o >>= 1)
                    s += __shfl_xor_sync(0xffffffffu, s, o);
                v[q] = s;
            }
            float Sre = v[0] * invS, Sim = v[1] * invS;
            float Nre = v[2] * invN, Nim = v[3] * invN;
            if (r == e) trN += Nre;
            if (lane == e)              col[r] = make_float2(Nre,  Nim);
            if (lane == r && r != e)    col[e] = make_float2(Nre, -Nim);
            if (lane == 8 + e)          col[r] = make_float2(Sre,  Sim);
            if (lane == 8 + r && r != e) col[e] = make_float2(Sre, -Sim);
        }
    }
    const float d = 1e-6f * trN + 1e-8f;
    #pragma unroll
    for (int i = 0; i < 8; i++)
        if (lane == i) col[i].x += d;

    // Gauss-Jordan on [A | B] (no pivoting: HPD + reg)
    #pragma unroll
    for (int k = 0; k < 8; k++) {
        float2 piv;
        piv.x = __shfl_sync(0xffffffffu, col[k].x, k);
        piv.y = __shfl_sync(0xffffffffu, col[k].y, k);
        float2 pinv = crecip(piv);
        col[k] = cmul(col[k], pinv);
        #pragma unroll
        for (int i = 0; i < 8; i++) {
            if (i == k) continue;
            float2 fct;
            fct.x = __shfl_sync(0xffffffffu, col[i].x, k);
            fct.y = __shfl_sync(0xffffffffu, col[i].y, k);
            float2 t2 = cmul(fct, col[k]);
            col[i].x -= t2.x; col[i].y -= t2.y;
        }
    }

    // trace of X (lane 8+i holds col[i] = X[i][i])
    float2 dg = make_float2(0.f, 0.f);
    #pragma unroll
    for (int i = 0; i < 8; i++)
        if (lane == 8 + i) dg = col[i];
    #pragma unroll
    for (int o = 16; o; o >>= 1) {
        dg.x += __shfl_xor_sync(0xffffffffu, dg.x, o);
        dg.y += __shfl_xor_sync(0xffffffffu, dg.y, o);
    }
    float2 cd = make_float2(1.0f + dg.x, -dg.y);   // conj(beta + tr(X))
    float2 E  = crecip(cd);                        // 1 / conj(denom)

    // G[m][c] = conj(X[c][m]) * E ; lane 8+m holds col[c] = X[c][m]
    if (lane >= 8 && lane < 16) {
        const int m = lane - 8;
        float2* Gp = (float2*)(d_G + (size_t)w * 128) + m * 8;
        #pragma unroll
        for (int c = 0; c < 8; c++) {
            float2 xc = make_float2(col[c].x, -col[c].y);
            Gp[c] = cmul(xc, E);
        }
    }
}

// ---- D: apply filter. block per (b,f); G pre-splatted in smem; thread per t-pair.
//      f32x2 lanes vectorize over TIME (t0,t1). PLANAR float32 (2,B,C,F,T) out ----
__global__ void __launch_bounds__(256)
kD(const float* __restrict__ re, const float* __restrict__ im,
   float* __restrict__ outf, long long caps, long long capoutf) {
    __shared__ float2 sGr[64];   // (gr, gr)   for (m,c) = idx
    __shared__ float2 sGi[64];   // (gi, gi)
    __shared__ float2 sGm[64];   // (-gi, -gi)
    const int bf  = blockIdx.x;
    const int b   = bf >> 9, f = bf & 511;
    const int tid = threadIdx.x;

    if (tid < 64) {
        float gr = d_G[(size_t)bf * 128 + tid * 2 + 0];
        float gi = d_G[(size_t)bf * 128 + tid * 2 + 1];
        sGr[tid] = make_float2(gr, gr);
        sGi[tid] = make_float2(gi, gi);
        sGm[tid] = make_float2(-gi, -gi);
    }
    __syncthreads();

    long long xb[8];
    #pragma unroll
    for (int c = 0; c < 8; c++)
        xb[c] = ((long long)(b * C_ + c) * F_ + f) * T_;
    const long long ob0 = ((long long)(b * C_) * F_ + f) * T_;

    for (int u = tid; u < T_ / 2; u += 256) {
        const int t = u * 2;
        float2 xr[8], xi[8];       // lanes = (t0, t1)
        #pragma unroll
        for (int c = 0; c < 8; c++) {
            xr[c] = gld2(re, xb[c] + t, caps);
            xi[c] = gld2(im, xb[c] + t, caps);
        }
        #pragma unroll
        for (int m = 0; m < 8; m++) {
            float2 ar = make_float2(0.f, 0.f);
            float2 ai = make_float2(0.f, 0.f);
            #pragma unroll
            for (int c = 0; c < 8; c++) {
                const int idx = m * 8 + c;
                ar = ffma2(sGr[idx], xr[c], ar);
                ar = ffma2(sGm[idx], xi[c], ar);   // -gi * xi
                ai = ffma2(sGr[idx], xi[c], ai);
                ai = ffma2(sGi[idx], xr[c], ai);
            }
            long long oc = ob0 + (long long)m * (F_ * T_) + t;
            gst2(outf, oc,          capoutf, ar);  // real plane
            gst2(outf, SPEC_N + oc, capoutf, ai);  // imag plane
        }
    }
}

extern "C" void kernel_launch(void* const* d_in, const int* in_sizes, int n_in,
                              void* d_out, int out_size) {
    if (n_in < 4 || !d_out) return;

    const float* re  = (const float*)d_in[0];
    const float* im  = (const float*)d_in[1];
    const float* mks = (const float*)d_in[2];
    const float* mkn = (const float*)d_in[3];
    long long cap_re = (long long)in_sizes[0];
    long long cap_im = (long long)in_sizes[1];
    long long caps   = cap_re < cap_im ? cap_re : cap_im;
    long long cm0 = (long long)in_sizes[2];
    long long cm1 = (long long)in_sizes[3];
    long long capm = cm0 < cm1 ? cm0 : cm1;
    long long capoutf = (long long)out_size;   // float32 element count (confirmed)

    kA<<<(NBF + 255) / 256, 256>>>(mks, mkn, capm);
    kB<<<dim3(NBF, 4), 64>>>(re, im, mks, mkn, caps, capm);
    kC<<<NBF / 8, 256>>>();
    kD<<<NBF, 256>>>(re, im, (float*)d_out, caps, capoutf);
}

// round 10
// speedup vs baseline: 4.0114x; 1.4760x over previous
#include <cuda_runtime.h>

#define B_ 4
#define C_ 8
#define F_ 512
#define T_ 1000

#define SPEC_N 16384000ll   // B*C*F*T
#define NBF    2048         // B*F

// triangle pair index for r <= e
#define IDX(r, e) ((r) * 8 + (e) - ((r) * ((r) + 1)) / 2)   // 0..35

// -------- device scratch --------
// reduced PSD partials: [bf][p36][q4][half2]  q: 0=S.re 1=S.im 2=N.re 3=N.im
__device__ __align__(16) float d_part2[(size_t)NBF * 288];
__device__ float d_msum[NBF * 4];   // [bf][half][s/n]

// ---------------- helpers ----------------
__device__ __forceinline__ float gldf(const float* p, long long i, long long cap) {
    return (i >= 0 && i < cap) ? p[i] : 0.0f;
}
__device__ __forceinline__ float4 gld4(const float* p, long long i, long long cap) {
    if (i >= 0 && i + 3 < cap && ((i & 3) == 0))
        return *(const float4*)(p + i);
    return make_float4(gldf(p, i, cap), gldf(p, i + 1, cap),
                       gldf(p, i + 2, cap), gldf(p, i + 3, cap));
}
__device__ __forceinline__ float2 cmul(float2 a, float2 b) {
    return make_float2(fmaf(a.x, b.x, -a.y * b.y), fmaf(a.x, b.y, a.y * b.x));
}
__device__ __forceinline__ float2 crecip(float2 a) {
    float inv = 1.0f / fmaf(a.x, a.x, a.y * a.y);
    return make_float2(a.x * inv, -a.y * inv);
}
__device__ __forceinline__ float2 wred2(float2 v) {
    #pragma unroll
    for (int o = 16; o; o >>= 1) {
        v.x += __shfl_xor_sync(0xffffffffu, v.x, o);
        v.y += __shfl_xor_sync(0xffffffffu, v.y, o);
    }
    return v;
}

// ---- K1: masked PSD (upper triangle) + mask sums. block=(bf, rq), 64 thr ----
template<int RQ>
__device__ __forceinline__ void k1_body(
    int bf, int half, int lane,
    const float* __restrict__ re, const float* __restrict__ im,
    const float* __restrict__ ms, const float* __restrict__ mn,
    long long caps, long long capm)
{
    constexpr int R1 = 7 - RQ;
    const int b = bf >> 9, f = bf & 511;
    const long long mb = (long long)bf * T_;
    long long xb[8];
    #pragma unroll
    for (int q = RQ; q < 8; q++)
        xb[q] = ((long long)(b * C_ + q) * F_ + f) * T_;

    // scalar complex accumulators (x = re, y = im)
    float2 a0S[8], a0N[8], a1S[8], a1N[8];
    #pragma unroll
    for (int e = RQ; e < 8; e++) { a0S[e] = make_float2(0.f, 0.f); a0N[e] = a0S[e]; }
    #pragma unroll
    for (int e = R1; e < 8; e++) { a1S[e] = make_float2(0.f, 0.f); a1N[e] = a1S[e]; }
    float ss = 0.f, sn = 0.f;

    const int i4beg = half * (T_ / 8) + lane;
    const int i4end = half ? (T_ / 4) : (T_ / 8);
    for (int i4 = i4beg; i4 < i4end; i4 += 32) {
        const int t = i4 * 4;
        float4 mS4 = gld4(ms, mb + t, capm);
        float4 mN4 = gld4(mn, mb + t, capm);
        if (RQ == 3) {   // fold mask sums (only one rq-slice does this)
            ss += (mS4.x + mS4.y) + (mS4.z + mS4.w);
            sn += (mN4.x + mN4.y) + (mN4.z + mN4.w);
        }
        float4 yr[8], yi[8];
        #pragma unroll
        for (int q = RQ; q < 8; q++) {
            yr[q] = gld4(re, xb[q] + t, caps);
            yi[q] = gld4(im, xb[q] + t, caps);
        }
        const float* mSa = &mS4.x; const float* mNa = &mN4.x;
        #pragma unroll
        for (int j = 0; j < 4; j++) {
            float mS = mSa[j], mN = mNa[j];
            {   // row RQ vs e = RQ..7
                float xr0 = (&yr[RQ].x)[j], xi0 = (&yi[RQ].x)[j];
                #pragma unroll
                for (int e = RQ; e < 8; e++) {
                    float yre = (&yr[e].x)[j], yie = (&yi[e].x)[j];
                    float cr = fmaf(xr0, yre,  xi0 * yie);   // x*conj(y)
                    float ci = fmaf(xi0, yre, -xr0 * yie);
                    a0S[e].x = fmaf(mS, cr, a0S[e].x);
                    a0S[e].y = fmaf(mS, ci, a0S[e].y);
                    a0N[e].x = fmaf(mN, cr, a0N[e].x);
                    a0N[e].y = fmaf(mN, ci, a0N[e].y);
                }
            }
            {   // row R1 vs e = R1..7
                float xr1 = (&yr[R1].x)[j], xi1 = (&yi[R1].x)[j];
                #pragma unroll
                for (int e = R1; e < 8; e++) {
                    float yre = (&yr[e].x)[j], yie = (&yi[e].x)[j];
                    float cr = fmaf(xr1, yre,  xi1 * yie);
                    float ci = fmaf(xi1, yre, -xr1 * yie);
                    a1S[e].x = fmaf(mS, cr, a1S[e].x);
                    a1S[e].y = fmaf(mS, ci, a1S[e].y);
                    a1N[e].x = fmaf(mN, cr, a1N[e].x);
                    a1N[e].y = fmaf(mN, ci, a1N[e].y);
                }
            }
        }
    }

    // warp-reduce and write tiny partials: [bf][p][q][half]
    #pragma unroll
    for (int e = RQ; e < 8; e++) {
        float2 vS = wred2(a0S[e]);
        float2 vN = wred2(a0N[e]);
        if (lane == 0) {
            size_t base = ((size_t)bf * 36 + IDX(RQ, e)) * 8 + half;
            d_part2[base + 0] = vS.x;
            d_part2[base + 2] = vS.y;
            d_part2[base + 4] = vN.x;
            d_part2[base + 6] = vN.y;
        }
    }
    #pragma unroll
    for (int e = R1; e < 8; e++) {
        float2 vS = wred2(a1S[e]);
        float2 vN = wred2(a1N[e]);
        if (lane == 0) {
            size_t base = ((size_t)bf * 36 + IDX(R1, e)) * 8 + half;
            d_part2[base + 0] = vS.x;
            d_part2[base + 2] = vS.y;
            d_part2[base + 4] = vN.x;
            d_part2[base + 6] = vN.y;
        }
    }
    if (RQ == 3) {
        float2 m2 = wred2(make_float2(ss, sn));
        if (lane == 0) {
            d_msum[bf * 4 + half * 2 + 0] = m2.x;
            d_msum[bf * 4 + half * 2 + 1] = m2.y;
        }
    }
}

__global__ void __launch_bounds__(64)
k1(const float* __restrict__ re, const float* __restrict__ im,
   const float* __restrict__ ms, const float* __restrict__ mn,
   long long caps, long long capm) {
    const int bf   = blockIdx.x;
    const int half = threadIdx.x >> 5;
    const int lane = threadIdx.x & 31;
    switch (blockIdx.y) {
        case 0: k1_body<0>(bf, half, lane, re, im, ms, mn, caps, capm); break;
        case 1: k1_body<1>(bf, half, lane, re, im, ms, mn, caps, capm); break;
        case 2: k1_body<2>(bf, half, lane, re, im, ms, mn, caps, capm); break;
        default: k1_body<3>(bf, half, lane, re, im, ms, mn, caps, capm); break;
    }
}

// ---- K2: block per (b,f). Phase 1: load PSD to smem. Phase 2: warp 0 solves.
//      Phase 3: all 256 threads apply filter (scalar, thread per t). ----
__global__ void __launch_bounds__(256)
k2(const float* __restrict__ re, const float* __restrict__ im,
   float* __restrict__ outf, long long caps, long long capoutf)
{
    __shared__ float sPsd[144];    // [p36][q4], halves summed
    __shared__ float2 sG[64];      // G[m][c] = conj(W[c][m]) as (re, im)
    __shared__ float sInv[2];      // 1/(mask_s sum + eps), 1/(mask_n sum + eps)

    const int bf  = blockIdx.x;
    const int b   = bf >> 9, f = bf & 511;
    const int tid = threadIdx.x;
    const int lane = tid & 31;

    if (tid < 144) {
        const float2 v = *(const float2*)&d_part2[(size_t)bf * 288 + tid * 2];
        sPsd[tid] = v.x + v.y;
    } else if (tid == 144) {
        sInv[0] = 1.0f / (d_msum[bf * 4 + 0] + d_msum[bf * 4 + 2] + 1e-10f);
    } else if (tid == 145) {
        sInv[1] = 1.0f / (d_msum[bf * 4 + 1] + d_msum[bf * 4 + 3] + 1e-10f);
    }
    __syncthreads();

    // ---- warp 0: warp-parallel Gauss-Jordan on [A | B] ----
    if (tid < 32) {
        const float invS = sInv[0], invN = sInv[1];
        const int jc  = lane & 7;
        const int isB = (lane >> 3) & 1;     // lanes 8..15 own B columns
        const float sc = isB ? invS : invN;
        const int qr = isB ? 0 : 2, qi = isB ? 1 : 3;

        float trN = 0.f;
        #pragma unroll
        for (int i = 0; i < 8; i++)
            trN += sPsd[IDX(i, i) * 4 + 2];
        trN *= invN;
        const float dreg = 1e-6f * trN + 1e-8f;

        float2 col[8];
        #pragma unroll
        for (int i = 0; i < 8; i++) {
            const int r = i < jc ? i : jc;
            const int e = i < jc ? jc : i;
            float vr = sPsd[IDX(r, e) * 4 + qr] * sc;
            float vi = sPsd[IDX(r, e) * 4 + qi] * sc;
            if (i > jc) vi = -vi;            // P[i][j] = conj(P[j][i])
            col[i] = make_float2(vr, vi);
            if (!isB && i == jc) col[i].x += dreg;
        }

        #pragma unroll
        for (int k = 0; k < 8; k++) {
            float2 piv;
            piv.x = __shfl_sync(0xffffffffu, col[k].x, k);
            piv.y = __shfl_sync(0xffffffffu, col[k].y, k);
            float2 pinv = crecip(piv);
            col[k] = cmul(col[k], pinv);
            #pragma unroll
            for (int i = 0; i < 8; i++) {
                if (i == k) continue;
                float2 fct;
                fct.x = __shfl_sync(0xffffffffu, col[i].x, k);
                fct.y = __shfl_sync(0xffffffffu, col[i].y, k);
                float2 t2 = cmul(fct, col[k]);
                col[i].x -= t2.x; col[i].y -= t2.y;
            }
        }

        // trace of X: lane 8+i holds col[i] = X[i][i]
        float2 dg = make_float2(0.f, 0.f);
        #pragma unroll
        for (int i = 0; i < 8; i++)
            if (lane == 8 + i) dg = col[i];
        dg = wred2(dg);
        float2 cd = make_float2(1.0f + dg.x, -dg.y);   // conj(beta + tr(X))
        float2 E  = crecip(cd);

        // G[m][c] = conj(X[c][m]) * E ; lane 8+m holds col[c] = X[c][m]
        if (lane >= 8 && lane < 16) {
            const int m = lane - 8;
            #pragma unroll
            for (int c = 0; c < 8; c++) {
                float2 xc = make_float2(col[c].x, -col[c].y);
                sG[m * 8 + c] = cmul(xc, E);
            }
        }
    }
    __syncthreads();

    // ---- apply: scalar, thread per t (proven high-occupancy form) ----
    long long xb[8];
    #pragma unroll
    for (int c = 0; c < 8; c++)
        xb[c] = ((long long)(b * C_ + c) * F_ + f) * T_;
    const long long ob0 = ((long long)(b * C_) * F_ + f) * T_;

    for (int t = tid; t < T_; t += 256) {
        float xr[8], xi[8];
        #pragma unroll
        for (int c = 0; c < 8; c++) {
            xr[c] = gldf(re, xb[c] + t, caps);
            xi[c] = gldf(im, xb[c] + t, caps);
        }
        #pragma unroll
        for (int m = 0; m < 8; m++) {
            float ar = 0.f, ai = 0.f;
            #pragma unroll
            for (int c = 0; c < 8; c++) {
                float2 g = sG[m * 8 + c];
                ar = fmaf(g.x, xr[c], ar);
                ar = fmaf(-g.y, xi[c], ar);
                ai = fmaf(g.x, xi[c], ai);
                ai = fmaf(g.y, xr[c], ai);
            }
            long long oc = ob0 + (long long)m * (F_ * T_) + t;
            if (oc >= 0 && oc < capoutf)                   outf[oc] = ar;
            if (SPEC_N + oc >= 0 && SPEC_N + oc < capoutf) outf[SPEC_N + oc] = ai;
        }
    }
}

extern "C" void kernel_launch(void* const* d_in, const int* in_sizes, int n_in,
                              void* d_out, int out_size) {
    if (n_in < 4 || !d_out) return;

    const float* re  = (const float*)d_in[0];
    const float* im  = (const float*)d_in[1];
    const float* mks = (const float*)d_in[2];
    const float* mkn = (const float*)d_in[3];
    long long cap_re = (long long)in_sizes[0];
    long long cap_im = (long long)in_sizes[1];
    long long caps   = cap_re < cap_im ? cap_re : cap_im;
    long long cm0 = (long long)in_sizes[2];
    long long cm1 = (long long)in_sizes[3];
    long long capm = cm0 < cm1 ? cm0 : cm1;
    long long capoutf = (long long)out_size;   // float32 element count (confirmed)

    k1<<<dim3(NBF, 4), 64>>>(re, im, mks, mkn, caps, capm);
    k2<<<NBF, 256>>>(re, im, (float*)d_out, caps, capoutf);
}

// round 11
// speedup vs baseline: 4.4003x; 1.0970x over previous
#include <cuda_runtime.h>

#define B_ 4
#define C_ 8
#define F_ 512
#define T_ 1000

#define SPEC_N 16384000ll   // B*C*F*T
#define NBF    2048         // B*F

// triangle pair index for r <= e
#define IDX(r, e) ((r) * 8 + (e) - ((r) * ((r) + 1)) / 2)   // 0..35

// -------- device scratch --------
// reduced PSD partials: [bf][p36][q4][half2]  q: 0=S.re 1=S.im 2=N.re 3=N.im
__device__ __align__(16) float d_part2[(size_t)NBF * 288];
__device__ float d_msum[NBF * 4];                       // [bf][half][s/n]
__device__ __align__(16) float d_G[(size_t)NBF * 128];  // [bf][m][c][2] : conj(W[c][m])

// ---------------- helpers ----------------
__device__ __forceinline__ float gldf(const float* p, long long i, long long cap) {
    return (i >= 0 && i < cap) ? p[i] : 0.0f;
}
__device__ __forceinline__ float4 gld4(const float* p, long long i, long long cap) {
    if (i >= 0 && i + 3 < cap && ((i & 3) == 0))
        return *(const float4*)(p + i);
    return make_float4(gldf(p, i, cap), gldf(p, i + 1, cap),
                       gldf(p, i + 2, cap), gldf(p, i + 3, cap));
}
__device__ __forceinline__ float2 cmul(float2 a, float2 b) {
    return make_float2(fmaf(a.x, b.x, -a.y * b.y), fmaf(a.x, b.y, a.y * b.x));
}
__device__ __forceinline__ float2 crecip(float2 a) {
    float inv = 1.0f / fmaf(a.x, a.x, a.y * a.y);
    return make_float2(a.x * inv, -a.y * inv);
}
__device__ __forceinline__ float2 wred2(float2 v) {
    #pragma unroll
    for (int o = 16; o; o >>= 1) {
        v.x += __shfl_xor_sync(0xffffffffu, v.x, o);
        v.y += __shfl_xor_sync(0xffffffffu, v.y, o);
    }
    return v;
}

// ---- K1: masked PSD (upper triangle) + mask sums. block=(bf, rq), 64 thr ----
template<int RQ>
__device__ __forceinline__ void k1_body(
    int bf, int half, int lane,
    const float* __restrict__ re, const float* __restrict__ im,
    const float* __restrict__ ms, const float* __restrict__ mn,
    long long caps, long long capm)
{
    constexpr int R1 = 7 - RQ;
    const int b = bf >> 9, f = bf & 511;
    const long long mb = (long long)bf * T_;
    long long xb[8];
    #pragma unroll
    for (int q = RQ; q < 8; q++)
        xb[q] = ((long long)(b * C_ + q) * F_ + f) * T_;

    float2 a0S[8], a0N[8], a1S[8], a1N[8];
    #pragma unroll
    for (int e = RQ; e < 8; e++) { a0S[e] = make_float2(0.f, 0.f); a0N[e] = a0S[e]; }
    #pragma unroll
    for (int e = R1; e < 8; e++) { a1S[e] = make_float2(0.f, 0.f); a1N[e] = a1S[e]; }
    float ss = 0.f, sn = 0.f;

    const int i4beg = half * (T_ / 8) + lane;
    const int i4end = half ? (T_ / 4) : (T_ / 8);
    for (int i4 = i4beg; i4 < i4end; i4 += 32) {
        const int t = i4 * 4;
        float4 mS4 = gld4(ms, mb + t, capm);
        float4 mN4 = gld4(mn, mb + t, capm);
        if (RQ == 3) {
            ss += (mS4.x + mS4.y) + (mS4.z + mS4.w);
            sn += (mN4.x + mN4.y) + (mN4.z + mN4.w);
        }
        float4 yr[8], yi[8];
        #pragma unroll
        for (int q = RQ; q < 8; q++) {
            yr[q] = gld4(re, xb[q] + t, caps);
            yi[q] = gld4(im, xb[q] + t, caps);
        }
        const float* mSa = &mS4.x; const float* mNa = &mN4.x;
        #pragma unroll
        for (int j = 0; j < 4; j++) {
            float mS = mSa[j], mN = mNa[j];
            {   // row RQ vs e = RQ..7
                float xr0 = (&yr[RQ].x)[j], xi0 = (&yi[RQ].x)[j];
                #pragma unroll
                for (int e = RQ; e < 8; e++) {
                    float yre = (&yr[e].x)[j], yie = (&yi[e].x)[j];
                    float cr = fmaf(xr0, yre,  xi0 * yie);   // x*conj(y)
                    float ci = fmaf(xi0, yre, -xr0 * yie);
                    a0S[e].x = fmaf(mS, cr, a0S[e].x);
                    a0S[e].y = fmaf(mS, ci, a0S[e].y);
                    a0N[e].x = fmaf(mN, cr, a0N[e].x);
                    a0N[e].y = fmaf(mN, ci, a0N[e].y);
                }
            }
            {   // row R1 vs e = R1..7
                float xr1 = (&yr[R1].x)[j], xi1 = (&yi[R1].x)[j];
                #pragma unroll
                for (int e = R1; e < 8; e++) {
                    float yre = (&yr[e].x)[j], yie = (&yi[e].x)[j];
                    float cr = fmaf(xr1, yre,  xi1 * yie);
                    float ci = fmaf(xi1, yre, -xr1 * yie);
                    a1S[e].x = fmaf(mS, cr, a1S[e].x);
                    a1S[e].y = fmaf(mS, ci, a1S[e].y);
                    a1N[e].x = fmaf(mN, cr, a1N[e].x);
                    a1N[e].y = fmaf(mN, ci, a1N[e].y);
                }
            }
        }
    }

    // warp-reduce; lane 0 writes tiny partials: [bf][p][q][half]
    #pragma unroll
    for (int e = RQ; e < 8; e++) {
        float2 vS = wred2(a0S[e]);
        float2 vN = wred2(a0N[e]);
        if (lane == 0) {
            size_t base = ((size_t)bf * 36 + IDX(RQ, e)) * 8 + half;
            d_part2[base + 0] = vS.x;
            d_part2[base + 2] = vS.y;
            d_part2[base + 4] = vN.x;
            d_part2[base + 6] = vN.y;
        }
    }
    #pragma unroll
    for (int e = R1; e < 8; e++) {
        float2 vS = wred2(a1S[e]);
        float2 vN = wred2(a1N[e]);
        if (lane == 0) {
            size_t base = ((size_t)bf * 36 + IDX(R1, e)) * 8 + half;
            d_part2[base + 0] = vS.x;
            d_part2[base + 2] = vS.y;
            d_part2[base + 4] = vN.x;
            d_part2[base + 6] = vN.y;
        }
    }
    if (RQ == 3) {
        float2 m2 = wred2(make_float2(ss, sn));
        if (lane == 0) {
            d_msum[bf * 4 + half * 2 + 0] = m2.x;
            d_msum[bf * 4 + half * 2 + 1] = m2.y;
        }
    }
}

__global__ void __launch_bounds__(64)
k1(const float* __restrict__ re, const float* __restrict__ im,
   const float* __restrict__ ms, const float* __restrict__ mn,
   long long caps, long long capm) {
    const int bf   = blockIdx.x;
    const int half = threadIdx.x >> 5;
    const int lane = threadIdx.x & 31;
    switch (blockIdx.y) {
        case 0: k1_body<0>(bf, half, lane, re, im, ms, mn, caps, capm); break;
        case 1: k1_body<1>(bf, half, lane, re, im, ms, mn, caps, capm); break;
        case 2: k1_body<2>(bf, half, lane, re, im, ms, mn, caps, capm); break;
        default: k1_body<3>(bf, half, lane, re, im, ms, mn, caps, capm); break;
    }
}

// ---- KS: solve only. one warp per (b,f); 8 warps per block ----
__global__ void __launch_bounds__(256)
kS() {
    const int w    = blockIdx.x * 8 + (threadIdx.x >> 5);   // bf
    const int lane = threadIdx.x & 31;

    const float invS = 1.0f / (d_msum[w * 4 + 0] + d_msum[w * 4 + 2] + 1e-10f);
    const float invN = 1.0f / (d_msum[w * 4 + 1] + d_msum[w * 4 + 3] + 1e-10f);

    const float* P = d_part2 + (size_t)w * 288;   // [p][q][half]

    // trace of psd_n (pre-normalization)
    float trN = 0.f;
    #pragma unroll
    for (int i = 0; i < 8; i++) {
        const float* q = P + IDX(i, i) * 8;
        trN += q[4] + q[5];
    }
    trN *= invN;
    const float dreg = 1e-6f * trN + 1e-8f;

    // lane j<8: column j of A (psd_n); lanes 8..15: column of B (psd_s)
    const int jc  = lane & 7;
    const int isB = (lane >> 3) & 1;
    const float sc = isB ? invS : invN;
    const int qo = isB ? 0 : 4;   // float offset of (q.re, q.im) pair

    float2 col[8];
    #pragma unroll
    for (int i = 0; i < 8; i++) {
        const int r = i < jc ? i : jc;
        const int e = i < jc ? jc : i;
        const float* q = P + IDX(r, e) * 8 + qo;
        float vr = (q[0] + q[1]) * sc;
        float vi = (q[2] + q[3]) * sc;
        if (i > jc) vi = -vi;                 // Hermitian reconstruction
        col[i] = make_float2(vr, vi);
        if (!isB && i == jc) col[i].x += dreg;
    }

    // Gauss-Jordan on [A | B] (no pivoting: HPD + reg)
    #pragma unroll
    for (int k = 0; k < 8; k++) {
        float2 piv;
        piv.x = __shfl_sync(0xffffffffu, col[k].x, k);
        piv.y = __shfl_sync(0xffffffffu, col[k].y, k);
        float2 pinv = crecip(piv);
        col[k] = cmul(col[k], pinv);
        #pragma unroll
        for (int i = 0; i < 8; i++) {
            if (i == k) continue;
            float2 fct;
            fct.x = __shfl_sync(0xffffffffu, col[i].x, k);
            fct.y = __shfl_sync(0xffffffffu, col[i].y, k);
            float2 t2 = cmul(fct, col[k]);
            col[i].x -= t2.x; col[i].y -= t2.y;
        }
    }

    // trace of X: lane 8+i holds col[i] = X[i][i]
    float2 dg = make_float2(0.f, 0.f);
    #pragma unroll
    for (int i = 0; i < 8; i++)
        if (lane == 8 + i) dg = col[i];
    dg = wred2(dg);
    float2 cd = make_float2(1.0f + dg.x, -dg.y);   // conj(beta + tr(X))
    float2 E  = crecip(cd);

    // G[m][c] = conj(X[c][m]) * E ; lane 8+m holds col[c] = X[c][m]
    if (lane >= 8 && lane < 16) {
        const int m = lane - 8;
        float2* Gp = (float2*)(d_G + (size_t)w * 128) + m * 8;
        #pragma unroll
        for (int c = 0; c < 8; c++) {
            float2 xc = make_float2(col[c].x, -col[c].y);
            Gp[c] = cmul(xc, E);
        }
    }
}

// ---- K2: apply only. block per (b,f); G staged in smem; scalar thread-per-t ----
__global__ void __launch_bounds__(256)
k2(const float* __restrict__ re, const float* __restrict__ im,
   float* __restrict__ outf, long long caps, long long capoutf)
{
    __shared__ float2 sG[64];
    const int bf  = blockIdx.x;
    const int b   = bf >> 9, f = bf & 511;
    const int tid = threadIdx.x;

    if (tid < 64)
        sG[tid] = *((const float2*)(d_G + (size_t)bf * 128) + tid);
    __syncthreads();

    long long xb[8];
    #pragma unroll
    for (int c = 0; c < 8; c++)
        xb[c] = ((long long)(b * C_ + c) * F_ + f) * T_;
    const long long ob0 = ((long long)(b * C_) * F_ + f) * T_;

    for (int t = tid; t < T_; t += 256) {
        float xr[8], xi[8];
        #pragma unroll
        for (int c = 0; c < 8; c++) {
            xr[c] = gldf(re, xb[c] + t, caps);
            xi[c] = gldf(im, xb[c] + t, caps);
        }
        #pragma unroll
        for (int m = 0; m < 8; m++) {
            float ar = 0.f, ai = 0.f;
            #pragma unroll
            for (int c = 0; c < 8; c++) {
                float2 g = sG[m * 8 + c];
                ar = fmaf(g.x, xr[c], ar);
                ar = fmaf(-g.y, xi[c], ar);
                ai = fmaf(g.x, xi[c], ai);
                ai = fmaf(g.y, xr[c], ai);
            }
            long long oc = ob0 + (long long)m * (F_ * T_) + t;
            if (oc >= 0 && oc < capoutf)                   outf[oc] = ar;
            if (SPEC_N + oc >= 0 && SPEC_N + oc < capoutf) outf[SPEC_N + oc] = ai;
        }
    }
}

extern "C" void kernel_launch(void* const* d_in, const int* in_sizes, int n_in,
                              void* d_out, int out_size) {
    if (n_in < 4 || !d_out) return;

    const float* re  = (const float*)d_in[0];
    const float* im  = (const float*)d_in[1];
    const float* mks = (const float*)d_in[2];
    const float* mkn = (const float*)d_in[3];
    long long cap_re = (long long)in_sizes[0];
    long long cap_im = (long long)in_sizes[1];
    long long caps   = cap_re < cap_im ? cap_re : cap_im;
    long long cm0 = (long long)in_sizes[2];
    long long cm1 = (long long)in_sizes[3];
    long long capm = cm0 < cm1 ? cm0 : cm1;
    long long capoutf = (long long)out_size;   // float32 element count (confirmed)

    k1<<<dim3(NBF, 4), 64>>>(re, im, mks, mkn, caps, capm);
    kS<<<NBF / 8, 256>>>();
    k2<<<NBF, 256>>>(re, im, (float*)d_out, caps, capoutf);
}